// round 2
// baseline (speedup 1.0000x reference)
#include <cuda_runtime.h>
#include <math.h>

#define Bt 4
#define Tt 2048
#define Dd 1024
#define Ee 8
#define Ff 2752
#define TOPK 2
#define Ntok (Bt*Tt)        // 8192 tokens
#define NR   (Ntok*TOPK)    // 16384 routed rows

// ---------------- device scratch (static globals; no allocs) ----------------
__device__ float g_h[(size_t)NR * Ff];     // SwiGLU intermediate, ~180 MB
__device__ float g_y[(size_t)NR * Dd];     // per-row down-proj output, ~67 MB
__device__ int   g_row_token[NR];          // routed row -> token
__device__ int   g_pos[Ntok * TOPK];       // (token,k) -> routed row
__device__ int   g_tok_eid[Ntok * TOPK];
__device__ float g_tok_w[Ntok * TOPK];
__device__ int   g_counts[Ee];
__device__ int   g_offs[Ee + 1];
__device__ int   g_cursor[Ee];
__device__ float g_load[Ee];

// ---------------- pass 0: zero per-launch metadata ----------------
__global__ void __launch_bounds__(32) zero_meta_kernel() {
    int t = threadIdx.x;
    if (t < Ee) { g_counts[t] = 0; g_load[t] = 0.0f; }
}

// ---------------- pass 1: gating (one warp per token) ----------------
__global__ void __launch_bounds__(128) gate_kernel(const float* __restrict__ x,
                                                   const float* __restrict__ gw) {
    int warp = (blockIdx.x * blockDim.x + threadIdx.x) >> 5;
    int lane = threadIdx.x & 31;
    if (warp >= Ntok) return;
    const float* xr = x + (size_t)warp * Dd;

    float xv[32];
#pragma unroll
    for (int j = 0; j < 32; j++) xv[j] = xr[j * 32 + lane];

    float p[Ee];
#pragma unroll
    for (int e = 0; e < Ee; e++) {
        float s = 0.0f;
#pragma unroll
        for (int j = 0; j < 32; j++) s += xv[j] * gw[(j * 32 + lane) * Ee + e];
#pragma unroll
        for (int o = 16; o; o >>= 1) s += __shfl_xor_sync(0xffffffffu, s, o);
        p[e] = s;
    }
    // softmax over 8 (redundant per lane)
    float mx = p[0];
#pragma unroll
    for (int e = 1; e < Ee; e++) mx = fmaxf(mx, p[e]);
    float den = 0.0f;
#pragma unroll
    for (int e = 0; e < Ee; e++) { p[e] = expf(p[e] - mx); den += p[e]; }
    float inv = 1.0f / den;
#pragma unroll
    for (int e = 0; e < Ee; e++) p[e] *= inv;

    // top-2, first-index tie-break (matches lax.top_k)
    int i1 = 0;
#pragma unroll
    for (int e = 1; e < Ee; e++) if (p[e] > p[i1]) i1 = e;
    int i2 = -1; float b2 = -1.0f;
#pragma unroll
    for (int e = 0; e < Ee; e++) {
        if (e == i1) continue;
        if (p[e] > b2) { b2 = p[e]; i2 = e; }
    }
    float s2 = p[i1] + p[i2] + 1e-8f;
    float w1 = p[i1] / s2, w2 = p[i2] / s2;

    if (lane == 0) {
        g_tok_eid[warp * 2 + 0] = i1;
        g_tok_eid[warp * 2 + 1] = i2;
        g_tok_w[warp * 2 + 0] = w1;
        g_tok_w[warp * 2 + 1] = w2;
        atomicAdd(&g_counts[i1], 1);
        atomicAdd(&g_counts[i2], 1);
#pragma unroll
        for (int e = 0; e < Ee; e++) atomicAdd(&g_load[e], p[e]);
    }
}

// ---------------- pass 2: tiny exclusive scan ----------------
__global__ void __launch_bounds__(32) scan_kernel() {
    if (threadIdx.x != 0) return;
    int s = 0;
    for (int e = 0; e < Ee; e++) {
        g_offs[e] = s; g_cursor[e] = s; s += g_counts[e];
    }
    g_offs[Ee] = s;  // == NR always
}

// ---------------- pass 3: routing build ----------------
__global__ void __launch_bounds__(256) build_kernel() {
    int t = blockIdx.x * blockDim.x + threadIdx.x;
    if (t >= Ntok) return;
#pragma unroll
    for (int k = 0; k < TOPK; k++) {
        int e = g_tok_eid[t * 2 + k];
        int r = atomicAdd(&g_cursor[e], 1);
        g_row_token[r] = t;
        g_pos[t * 2 + k] = r;
    }
}

// ---------------- GEMM tiles ----------------
#define BM 64
#define BN 64
#define BK 16

// pass 4: h = silu(Xg @ Wg[e]) * (Xg @ Wu[e])   (gathered rows)
__global__ void __launch_bounds__(256)
gemm1_kernel(const float* __restrict__ x,
             const float* __restrict__ wg,
             const float* __restrict__ wu) {
    int e = blockIdx.z;
    int off = g_offs[e], end = g_offs[e + 1];
    int rowStart = off + blockIdx.y * BM;
    if (rowStart >= end) return;
    int n0 = blockIdx.x * BN;
    const float* wge = wg + (size_t)e * Dd * Ff;
    const float* wue = wu + (size_t)e * Dd * Ff;

    __shared__ float As[BK][BM];
    __shared__ float Bs1[BK][BN];
    __shared__ float Bs2[BK][BN];

    int tid = threadIdx.x;
    int tx = tid & 15, ty = tid >> 4;
    float acc1[4][4] = {}, acc2[4][4] = {};

    int am = tid >> 2, akq = (tid & 3) * 4;       // A: 64 rows x 16 k
    int arow = rowStart + am;
    const float* axp = (arow < end) ? (x + (size_t)g_row_token[arow] * Dd) : nullptr;
    int bk = tid >> 4, bnq = (tid & 15) * 4;      // B: 16 k x 64 n

    for (int k0 = 0; k0 < Dd; k0 += BK) {
        float4 av = make_float4(0.f, 0.f, 0.f, 0.f);
        if (axp) av = *(const float4*)(axp + k0 + akq);
        As[akq + 0][am] = av.x; As[akq + 1][am] = av.y;
        As[akq + 2][am] = av.z; As[akq + 3][am] = av.w;
        *(float4*)&Bs1[bk][bnq] = *(const float4*)(wge + (size_t)(k0 + bk) * Ff + n0 + bnq);
        *(float4*)&Bs2[bk][bnq] = *(const float4*)(wue + (size_t)(k0 + bk) * Ff + n0 + bnq);
        __syncthreads();
#pragma unroll
        for (int k = 0; k < BK; k++) {
            float4 a  = *(float4*)&As[k][ty * 4];
            float4 b1 = *(float4*)&Bs1[k][tx * 4];
            float4 b2 = *(float4*)&Bs2[k][tx * 4];
            float ar[4] = {a.x, a.y, a.z, a.w};
            float b1r[4] = {b1.x, b1.y, b1.z, b1.w};
            float b2r[4] = {b2.x, b2.y, b2.z, b2.w};
#pragma unroll
            for (int i = 0; i < 4; i++)
#pragma unroll
                for (int j = 0; j < 4; j++) {
                    acc1[i][j] += ar[i] * b1r[j];
                    acc2[i][j] += ar[i] * b2r[j];
                }
        }
        __syncthreads();
    }
#pragma unroll
    for (int i = 0; i < 4; i++) {
        int r = rowStart + ty * 4 + i;
        if (r >= end) break;
        float* hp = g_h + (size_t)r * Ff + n0 + tx * 4;
#pragma unroll
        for (int j = 0; j < 4; j++) {
            float z = acc1[i][j];
            float s = z / (1.0f + expf(-z));   // silu
            hp[j] = s * acc2[i][j];
        }
    }
}

// pass 5: y = h @ Wd[e]
__global__ void __launch_bounds__(256)
gemm2_kernel(const float* __restrict__ wd) {
    int e = blockIdx.z;
    int off = g_offs[e], end = g_offs[e + 1];
    int rowStart = off + blockIdx.y * BM;
    if (rowStart >= end) return;
    int n0 = blockIdx.x * BN;
    const float* wde = wd + (size_t)e * Ff * Dd;

    __shared__ float As[BK][BM];
    __shared__ float Bs[BK][BN];

    int tid = threadIdx.x;
    int tx = tid & 15, ty = tid >> 4;
    float acc[4][4] = {};

    int am = tid >> 2, akq = (tid & 3) * 4;
    int arow = rowStart + am;
    const float* axp = (arow < end) ? (g_h + (size_t)arow * Ff) : nullptr;
    int bk = tid >> 4, bnq = (tid & 15) * 4;

    for (int k0 = 0; k0 < Ff; k0 += BK) {
        float4 av = make_float4(0.f, 0.f, 0.f, 0.f);
        if (axp) av = *(const float4*)(axp + k0 + akq);
        As[akq + 0][am] = av.x; As[akq + 1][am] = av.y;
        As[akq + 2][am] = av.z; As[akq + 3][am] = av.w;
        *(float4*)&Bs[bk][bnq] = *(const float4*)(wde + (size_t)(k0 + bk) * Dd + n0 + bnq);
        __syncthreads();
#pragma unroll
        for (int k = 0; k < BK; k++) {
            float4 a = *(float4*)&As[k][ty * 4];
            float4 b = *(float4*)&Bs[k][tx * 4];
            float ar[4] = {a.x, a.y, a.z, a.w};
            float br[4] = {b.x, b.y, b.z, b.w};
#pragma unroll
            for (int i = 0; i < 4; i++)
#pragma unroll
                for (int j = 0; j < 4; j++)
                    acc[i][j] += ar[i] * br[j];
        }
        __syncthreads();
    }
#pragma unroll
    for (int i = 0; i < 4; i++) {
        int r = rowStart + ty * 4 + i;
        if (r >= end) break;
        *(float4*)(g_y + (size_t)r * Dd + n0 + tx * 4) =
            make_float4(acc[i][0], acc[i][1], acc[i][2], acc[i][3]);
    }
}

// pass 6: out[t] = w0*y[pos0] + w1*y[pos1]  (deterministic, grid-stride)
__global__ void __launch_bounds__(256) combine_kernel(float* __restrict__ out) {
    const int nq = Ntok * (Dd / 4);
    for (int idx = blockIdx.x * blockDim.x + threadIdx.x; idx < nq;
         idx += gridDim.x * blockDim.x) {
        int t = idx / (Dd / 4);
        int dq = idx - t * (Dd / 4);
        int p0 = g_pos[t * 2 + 0], p1 = g_pos[t * 2 + 1];
        float w0 = g_tok_w[t * 2 + 0], w1 = g_tok_w[t * 2 + 1];
        float4 a = *(const float4*)(g_y + (size_t)p0 * Dd + dq * 4);
        float4 b = *(const float4*)(g_y + (size_t)p1 * Dd + dq * 4);
        float4 o;
        o.x = w0 * a.x + w1 * b.x;
        o.y = w0 * a.y + w1 * b.y;
        o.z = w0 * a.z + w1 * b.z;
        o.w = w0 * a.w + w1 * b.w;
        *(float4*)(out + (size_t)t * Dd + dq * 4) = o;
    }
}

// pass 7: aux loss into trailing output element(s)
__global__ void __launch_bounds__(32) aux_kernel(float* __restrict__ out, int out_size) {
    if (threadIdx.x != 0 || blockIdx.x != 0) return;
    float s = 0.0f;
    for (int e = 0; e < Ee; e++) {
        float load = g_load[e] / (float)Ntok;
        float frac = (float)g_counts[e] / (float)(Ntok * TOPK);
        s += frac * load;
    }
    float aux = 0.01f * (float)Ee * s;
    for (int i = Ntok * Dd; i < out_size; i++) out[i] = aux;
}

extern "C" void kernel_launch(void* const* d_in, const int* in_sizes, int n_in,
                              void* d_out, int out_size) {
    const float* x      = (const float*)d_in[0];
    const float* gate_w = (const float*)d_in[1];
    const float* w_gate = (const float*)d_in[2];
    const float* w_up   = (const float*)d_in[3];
    const float* w_down = (const float*)d_in[4];
    float* out = (float*)d_out;

    zero_meta_kernel<<<1, 32>>>();
    gate_kernel<<<Ntok / 4, 128>>>(x, gate_w);
    scan_kernel<<<1, 32>>>();
    build_kernel<<<(Ntok + 255) / 256, 256>>>();

    dim3 g1(Ff / BN, (NR + BM - 1) / BM, Ee);
    gemm1_kernel<<<g1, 256>>>(x, w_gate, w_up);

    dim3 g2(Dd / BN, (NR + BM - 1) / BM, Ee);
    gemm2_kernel<<<g2, 256>>>(w_down);

    combine_kernel<<<1184, 256>>>(out);
    aux_kernel<<<1, 32>>>(out, out_size);
}

// round 4
// speedup vs baseline: 2.3390x; 2.3390x over previous
#include <cuda_runtime.h>
#include <cuda_bf16.h>
#include <stdint.h>
#include <math.h>

#define Bt 4
#define Tt 2048
#define Dd 1024
#define Ee 8
#define Ff 2752
#define TOPK 2
#define Ntok (Bt*Tt)        // 8192 tokens
#define NR   (Ntok*TOPK)    // 16384 routed rows

// ======================= device scratch (static, no allocs) =======================
__device__ __nv_bfloat16 g_x_hi[(size_t)Ntok * Dd];
__device__ __nv_bfloat16 g_x_lo[(size_t)Ntok * Dd];
__device__ __nv_bfloat16 g_wg_hi[(size_t)Ee * Ff * Dd];   // [e][n(F)][k(D)]
__device__ __nv_bfloat16 g_wg_lo[(size_t)Ee * Ff * Dd];
__device__ __nv_bfloat16 g_wu_hi[(size_t)Ee * Ff * Dd];
__device__ __nv_bfloat16 g_wu_lo[(size_t)Ee * Ff * Dd];
__device__ __nv_bfloat16 g_wd_hi[(size_t)Ee * Dd * Ff];   // [e][n(D)][k(F)]
__device__ __nv_bfloat16 g_wd_lo[(size_t)Ee * Dd * Ff];
__device__ __nv_bfloat16 g_h_hi[(size_t)NR * Ff];         // [r][f]
__device__ __nv_bfloat16 g_h_lo[(size_t)NR * Ff];
__device__ float g_y[(size_t)NR * Dd];
__device__ int   g_row_token[NR];
__device__ int   g_pos[Ntok * TOPK];
__device__ int   g_tok_eid[Ntok * TOPK];
__device__ float g_tok_w[Ntok * TOPK];
__device__ int   g_counts[Ee];
__device__ int   g_offs[Ee + 1];
__device__ int   g_cursor[Ee];
__device__ int   g_tile_off[Ee + 1];
__device__ float g_load[Ee];

// ======================= helpers =======================
__device__ __forceinline__ uint32_t smem_u32(const void* p) {
    uint32_t a;
    asm("{ .reg .u64 t; cvta.to.shared.u64 t, %1; cvt.u32.u64 %0, t; }" : "=r"(a) : "l"(p));
    return a;
}

#define CPASYNC(dst, src) \
    asm volatile("cp.async.cg.shared.global [%0], [%1], 16;" :: "r"(dst), "l"(src) : "memory")
#define CPCOMMIT() asm volatile("cp.async.commit_group;" ::: "memory")
#define CPWAIT1()  asm volatile("cp.async.wait_group 1;" ::: "memory")
#define CPWAIT0()  asm volatile("cp.async.wait_group 0;" ::: "memory")

#define LDS32(v, a) asm volatile("ld.shared.b32 %0, [%1];" : "=r"(v) : "r"(a))

#define MMA_BF16(c, a, b) \
    asm volatile("mma.sync.aligned.m16n8k16.row.col.f32.bf16.bf16.f32 " \
        "{%0,%1,%2,%3}, {%4,%5,%6,%7}, {%8,%9}, {%0,%1,%2,%3};" \
        : "+f"((c)[0]), "+f"((c)[1]), "+f"((c)[2]), "+f"((c)[3]) \
        : "r"((a)[0]), "r"((a)[1]), "r"((a)[2]), "r"((a)[3]), "r"((b)[0]), "r"((b)[1]))

// padded row stride: 32 halves + 8 pad = 40 halves = 80 bytes (16B-aligned, conflict-free)
#define RSTR 80
#define A_TILE_B (128 * RSTR)        // 10240
#define B_TILE_B (64 * RSTR)         // 5120
#define G1_STAGE (2 * A_TILE_B + 4 * B_TILE_B)   // 40960
#define G2_STAGE (2 * A_TILE_B + 2 * (128 * RSTR))  // 40960
#define SMEM_TOT (2 * 40960 + 512)

// ======================= pass 0: zero metadata =======================
__global__ void __launch_bounds__(32) zero_meta_kernel() {
    int t = threadIdx.x;
    if (t < Ee) { g_counts[t] = 0; g_load[t] = 0.0f; }
}

// ======================= prep: split x to bf16 hi/lo =======================
__global__ void __launch_bounds__(256) split_x_kernel(const float* __restrict__ x) {
    int i = (blockIdx.x * 256 + threadIdx.x) * 4;
    if (i >= Ntok * Dd) return;
    float4 v = *(const float4*)(x + i);
    float vv[4] = {v.x, v.y, v.z, v.w};
    __nv_bfloat16 hh[4], ll[4];
#pragma unroll
    for (int q = 0; q < 4; q++) {
        hh[q] = __float2bfloat16(vv[q]);
        ll[q] = __float2bfloat16(vv[q] - __bfloat162float(hh[q]));
    }
    *(uint2*)(g_x_hi + i) = *(uint2*)hh;
    *(uint2*)(g_x_lo + i) = *(uint2*)ll;
}

// ======================= prep: transpose + split weights =======================
// src: [z][K][N] row-major -> dst: [z][N][K]  (hi/lo bf16)
__global__ void __launch_bounds__(256) tsplit_kernel(const float* __restrict__ src,
                                                     __nv_bfloat16* __restrict__ dhi,
                                                     __nv_bfloat16* __restrict__ dlo,
                                                     int K, int N) {
    __shared__ float t[32][33];
    size_t base = (size_t)blockIdx.z * K * N;
    int n0 = blockIdx.x * 32, k0 = blockIdx.y * 32;
#pragma unroll
    for (int i = 0; i < 4; i++) {
        int k = k0 + threadIdx.y + i * 8;
        t[threadIdx.y + i * 8][threadIdx.x] = src[base + (size_t)k * N + n0 + threadIdx.x];
    }
    __syncthreads();
#pragma unroll
    for (int i = 0; i < 4; i++) {
        int n = n0 + threadIdx.y + i * 8;
        float v = t[threadIdx.x][threadIdx.y + i * 8];
        __nv_bfloat16 hi = __float2bfloat16(v);
        size_t o = base + (size_t)n * K + k0 + threadIdx.x;
        dhi[o] = hi;
        dlo[o] = __float2bfloat16(v - __bfloat162float(hi));
    }
}

// ======================= gating (one warp per token, exact fp32) =======================
__global__ void __launch_bounds__(128) gate_kernel(const float* __restrict__ x,
                                                   const float* __restrict__ gw) {
    int warp = (blockIdx.x * blockDim.x + threadIdx.x) >> 5;
    int lane = threadIdx.x & 31;
    if (warp >= Ntok) return;
    const float* xr = x + (size_t)warp * Dd;
    float xv[32];
#pragma unroll
    for (int j = 0; j < 32; j++) xv[j] = xr[j * 32 + lane];
    float p[Ee];
#pragma unroll
    for (int e = 0; e < Ee; e++) {
        float s = 0.0f;
#pragma unroll
        for (int j = 0; j < 32; j++) s += xv[j] * gw[(j * 32 + lane) * Ee + e];
#pragma unroll
        for (int o = 16; o; o >>= 1) s += __shfl_xor_sync(0xffffffffu, s, o);
        p[e] = s;
    }
    float mx = p[0];
#pragma unroll
    for (int e = 1; e < Ee; e++) mx = fmaxf(mx, p[e]);
    float den = 0.0f;
#pragma unroll
    for (int e = 0; e < Ee; e++) { p[e] = expf(p[e] - mx); den += p[e]; }
    float inv = 1.0f / den;
#pragma unroll
    for (int e = 0; e < Ee; e++) p[e] *= inv;
    int i1 = 0;
#pragma unroll
    for (int e = 1; e < Ee; e++) if (p[e] > p[i1]) i1 = e;
    int i2 = -1; float b2 = -1.0f;
#pragma unroll
    for (int e = 0; e < Ee; e++) {
        if (e == i1) continue;
        if (p[e] > b2) { b2 = p[e]; i2 = e; }
    }
    float s2 = p[i1] + p[i2] + 1e-8f;
    if (lane == 0) {
        g_tok_eid[warp * 2 + 0] = i1;
        g_tok_eid[warp * 2 + 1] = i2;
        g_tok_w[warp * 2 + 0] = p[i1] / s2;
        g_tok_w[warp * 2 + 1] = p[i2] / s2;
        atomicAdd(&g_counts[i1], 1);
        atomicAdd(&g_counts[i2], 1);
#pragma unroll
        for (int e = 0; e < Ee; e++) atomicAdd(&g_load[e], p[e]);
    }
}

// ======================= scan =======================
__global__ void __launch_bounds__(32) scan_kernel() {
    if (threadIdx.x != 0) return;
    int s = 0, ts = 0;
    for (int e = 0; e < Ee; e++) {
        g_offs[e] = s; g_cursor[e] = s; g_tile_off[e] = ts;
        ts += (g_counts[e] + 127) / 128;
        s += g_counts[e];
    }
    g_offs[Ee] = s; g_tile_off[Ee] = ts;
}

// ======================= routing build =======================
__global__ void __launch_bounds__(256) build_kernel() {
    int t = blockIdx.x * blockDim.x + threadIdx.x;
    if (t >= Ntok) return;
#pragma unroll
    for (int k = 0; k < TOPK; k++) {
        int e = g_tok_eid[t * 2 + k];
        int r = atomicAdd(&g_cursor[e], 1);
        g_row_token[r] = t;
        g_pos[t * 2 + k] = r;
    }
}

// ======================= gemm1: h = silu(Xg Wg) * (Xg Wu), mma.sync 3xbf16 =======================
// CTA: 256 thr (8 warps), tile M=128 x N=64(gate)+64(up), BK=32, 32 K-iters.
// warp: mw=wid&3 (32 rows), nw=wid>>2 (32 cols); per warp 32x32 gate + 32x32 up.
extern "C" __global__ void __launch_bounds__(256)
gemm1_mma_kernel() {
    extern __shared__ __align__(16) char smem[];
    int tid = threadIdx.x, wid = tid >> 5, lane = tid & 31;
    int grp = lane >> 2, tig = lane & 3;

    int j = blockIdx.y;
    if (j >= g_tile_off[Ee]) return;
    int e = 0;
#pragma unroll
    for (int q = 0; q < Ee - 1; q++) if (j >= g_tile_off[q + 1]) e = q + 1;
    int mt0 = j - g_tile_off[e];
    int rowStart = g_offs[e] + mt0 * 128;
    int end = g_offs[e + 1];
    int n0 = blockIdx.x * 64;

    uint32_t sb = smem_u32(smem);
    int* tokS = (int*)(smem + 2 * G1_STAGE);
    if (tid < 128) {
        int rr = rowStart + tid; if (rr > end - 1) rr = end - 1;
        tokS[tid] = g_row_token[rr];
    }
    __syncthreads();

    const __nv_bfloat16* wb[4];
    wb[0] = g_wg_hi + ((size_t)e * Ff + n0) * Dd;
    wb[1] = g_wg_lo + ((size_t)e * Ff + n0) * Dd;
    wb[2] = g_wu_hi + ((size_t)e * Ff + n0) * Dd;
    wb[3] = g_wu_lo + ((size_t)e * Ff + n0) * Dd;

    float cg[2][4][4] = {}, cu[2][4][4] = {};
    const int NIT = Dd / 32;   // 32

    // --- async copy of one stage ---
    auto issue = [&](int it) {
        char* st = smem + (it & 1) * G1_STAGE;
        uint32_t stu = sb + (it & 1) * G1_STAGE;
        int k0 = it * 32;
        (void)st;
#pragma unroll
        for (int q = 0; q < 8; q++) {
            int c = tid + q * 256;
            if (c < 1024) {                     // A hi/lo: 2*128 rows * 4 chunks
                int arr = c >> 9, idx = c & 511, row = idx >> 2, cc = idx & 3;
                const __nv_bfloat16* src =
                    (arr ? g_x_lo : g_x_hi) + (size_t)tokS[row] * Dd + k0 + cc * 8;
                uint32_t dst = stu + arr * A_TILE_B + row * RSTR + cc * 16;
                CPASYNC(dst, src);
            } else {                            // B: 4 mats * 64 rows * 4 chunks
                int b = c - 1024, mat = b >> 8, idx = b & 255, row = idx >> 2, cc = idx & 3;
                const __nv_bfloat16* src = wb[mat] + (size_t)row * Dd + k0 + cc * 8;
                uint32_t dst = stu + 2 * A_TILE_B + mat * B_TILE_B + row * RSTR + cc * 16;
                CPASYNC(dst, src);
            }
        }
        CPCOMMIT();
    };

    issue(0);
    for (int it = 0; it < NIT; it++) {
        if (it + 1 < NIT) { issue(it + 1); CPWAIT1(); } else { CPWAIT0(); }
        __syncthreads();
        uint32_t stu = sb + (it & 1) * G1_STAGE;
#pragma unroll
        for (int ks = 0; ks < 2; ks++) {
            int k16 = ks * 16;
            uint32_t ah[2][4], al[2][4];
#pragma unroll
            for (int mt = 0; mt < 2; mt++) {
                int row = (wid & 3) * 32 + mt * 16 + grp;
                uint32_t ab = stu + row * RSTR + k16 * 2 + tig * 4;
                LDS32(ah[mt][0], ab);       LDS32(ah[mt][1], ab + 8 * RSTR);
                LDS32(ah[mt][2], ab + 16);  LDS32(ah[mt][3], ab + 8 * RSTR + 16);
                ab += A_TILE_B;
                LDS32(al[mt][0], ab);       LDS32(al[mt][1], ab + 8 * RSTR);
                LDS32(al[mt][2], ab + 16);  LDS32(al[mt][3], ab + 8 * RSTR + 16);
            }
#pragma unroll
            for (int nt = 0; nt < 4; nt++) {
                int nrow = (wid >> 2) * 32 + nt * 8 + grp;
                uint32_t bbase = stu + 2 * A_TILE_B + nrow * RSTR + k16 * 2 + tig * 4;
                uint32_t bgh[2], bgl[2], buh[2], bul[2];
                LDS32(bgh[0], bbase);                    LDS32(bgh[1], bbase + 16);
                LDS32(bgl[0], bbase + B_TILE_B);         LDS32(bgl[1], bbase + B_TILE_B + 16);
                LDS32(buh[0], bbase + 2 * B_TILE_B);     LDS32(buh[1], bbase + 2 * B_TILE_B + 16);
                LDS32(bul[0], bbase + 3 * B_TILE_B);     LDS32(bul[1], bbase + 3 * B_TILE_B + 16);
#pragma unroll
                for (int mt = 0; mt < 2; mt++) {
                    MMA_BF16(cg[mt][nt], ah[mt], bgh);
                    MMA_BF16(cg[mt][nt], al[mt], bgh);
                    MMA_BF16(cg[mt][nt], ah[mt], bgl);
                    MMA_BF16(cu[mt][nt], ah[mt], buh);
                    MMA_BF16(cu[mt][nt], al[mt], buh);
                    MMA_BF16(cu[mt][nt], ah[mt], bul);
                }
            }
        }
        __syncthreads();
    }

    // epilogue: SwiGLU, split to bf16 hi/lo, store
#pragma unroll
    for (int mt = 0; mt < 2; mt++) {
#pragma unroll
        for (int half = 0; half < 2; half++) {   // c0/c1 vs c2/c3 (row, row+8)
            int row = rowStart + (wid & 3) * 32 + mt * 16 + grp + half * 8;
            if (row >= end) continue;
#pragma unroll
            for (int nt = 0; nt < 4; nt++) {
                int col = n0 + (wid >> 2) * 32 + nt * 8 + tig * 2;
                float g0 = cg[mt][nt][half * 2], g1 = cg[mt][nt][half * 2 + 1];
                float u0 = cu[mt][nt][half * 2], u1 = cu[mt][nt][half * 2 + 1];
                float z0 = g0 / (1.0f + expf(-g0)) * u0;
                float z1 = g1 / (1.0f + expf(-g1)) * u1;
                __nv_bfloat16 h0 = __float2bfloat16(z0);
                __nv_bfloat16 h1 = __float2bfloat16(z1);
                __nv_bfloat16 l0 = __float2bfloat16(z0 - __bfloat162float(h0));
                __nv_bfloat16 l1 = __float2bfloat16(z1 - __bfloat162float(h1));
                __nv_bfloat162 hv; hv.x = h0; hv.y = h1;
                __nv_bfloat162 lv; lv.x = l0; lv.y = l1;
                *(__nv_bfloat162*)(g_h_hi + (size_t)row * Ff + col) = hv;
                *(__nv_bfloat162*)(g_h_lo + (size_t)row * Ff + col) = lv;
            }
        }
    }
}

// ======================= gemm2: y = h @ Wd, mma.sync 3xbf16 =======================
// CTA: 256 thr, tile M=128 x N=128, BK=32, 86 K-iters. warp: mw=wid&3, nw=wid>>2 (64 cols)
extern "C" __global__ void __launch_bounds__(256)
gemm2_mma_kernel() {
    extern __shared__ __align__(16) char smem[];
    int tid = threadIdx.x, wid = tid >> 5, lane = tid & 31;
    int grp = lane >> 2, tig = lane & 3;

    int j = blockIdx.y;
    if (j >= g_tile_off[Ee]) return;
    int e = 0;
#pragma unroll
    for (int q = 0; q < Ee - 1; q++) if (j >= g_tile_off[q + 1]) e = q + 1;
    int mt0 = j - g_tile_off[e];
    int rowStart = g_offs[e] + mt0 * 128;
    int end = g_offs[e + 1];
    int n0 = blockIdx.x * 128;

    uint32_t sb = smem_u32(smem);
    const __nv_bfloat16* wdh = g_wd_hi + ((size_t)e * Dd + n0) * Ff;
    const __nv_bfloat16* wdl = g_wd_lo + ((size_t)e * Dd + n0) * Ff;

    float cc_[2][8][4] = {};
    const int NIT = Ff / 32;    // 86
    const int BT = 128 * RSTR;  // B tile bytes per hi/lo = 10240

    auto issue = [&](int it) {
        uint32_t stu = sb + (it & 1) * G2_STAGE;
        int k0 = it * 32;
#pragma unroll
        for (int q = 0; q < 8; q++) {
            int c = tid + q * 256;
            if (c < 1024) {                     // A (h) hi/lo
                int arr = c >> 9, idx = c & 511, row = idx >> 2, ck = idx & 3;
                int rr = rowStart + row; if (rr > end - 1) rr = end - 1;
                const __nv_bfloat16* src =
                    (arr ? g_h_lo : g_h_hi) + (size_t)rr * Ff + k0 + ck * 8;
                uint32_t dst = stu + arr * A_TILE_B + row * RSTR + ck * 16;
                CPASYNC(dst, src);
            } else {                            // B (wd) hi/lo: 2*128 rows * 4 chunks
                int b = c - 1024, arr = b >> 9, idx = b & 511, row = idx >> 2, ck = idx & 3;
                const __nv_bfloat16* src = (arr ? wdl : wdh) + (size_t)row * Ff + k0 + ck * 8;
                uint32_t dst = stu + 2 * A_TILE_B + arr * BT + row * RSTR + ck * 16;
                CPASYNC(dst, src);
            }
        }
        CPCOMMIT();
    };

    issue(0);
    for (int it = 0; it < NIT; it++) {
        if (it + 1 < NIT) { issue(it + 1); CPWAIT1(); } else { CPWAIT0(); }
        __syncthreads();
        uint32_t stu = sb + (it & 1) * G2_STAGE;
#pragma unroll
        for (int ks = 0; ks < 2; ks++) {
            int k16 = ks * 16;
            uint32_t ah[2][4], al[2][4];
#pragma unroll
            for (int mt = 0; mt < 2; mt++) {
                int row = (wid & 3) * 32 + mt * 16 + grp;
                uint32_t ab = stu + row * RSTR + k16 * 2 + tig * 4;
                LDS32(ah[mt][0], ab);       LDS32(ah[mt][1], ab + 8 * RSTR);
                LDS32(ah[mt][2], ab + 16);  LDS32(ah[mt][3], ab + 8 * RSTR + 16);
                ab += A_TILE_B;
                LDS32(al[mt][0], ab);       LDS32(al[mt][1], ab + 8 * RSTR);
                LDS32(al[mt][2], ab + 16);  LDS32(al[mt][3], ab + 8 * RSTR + 16);
            }
#pragma unroll
            for (int nt = 0; nt < 8; nt++) {
                int nrow = (wid >> 2) * 64 + nt * 8 + grp;
                uint32_t bbase = stu + 2 * A_TILE_B + nrow * RSTR + k16 * 2 + tig * 4;
                uint32_t bh[2], bl[2];
                LDS32(bh[0], bbase);        LDS32(bh[1], bbase + 16);
                LDS32(bl[0], bbase + BT);   LDS32(bl[1], bbase + BT + 16);
#pragma unroll
                for (int mt = 0; mt < 2; mt++) {
                    MMA_BF16(cc_[mt][nt], ah[mt], bh);
                    MMA_BF16(cc_[mt][nt], al[mt], bh);
                    MMA_BF16(cc_[mt][nt], ah[mt], bl);
                }
            }
        }
        __syncthreads();
    }

#pragma unroll
    for (int mt = 0; mt < 2; mt++) {
#pragma unroll
        for (int half = 0; half < 2; half++) {
            int row = rowStart + (wid & 3) * 32 + mt * 16 + grp + half * 8;
            if (row >= end) continue;
#pragma unroll
            for (int nt = 0; nt < 8; nt++) {
                int col = n0 + (wid >> 2) * 64 + nt * 8 + tig * 2;
                float2 v = make_float2(cc_[mt][nt][half * 2], cc_[mt][nt][half * 2 + 1]);
                *(float2*)(g_y + (size_t)row * Dd + col) = v;
            }
        }
    }
}

// ======================= combine =======================
__global__ void __launch_bounds__(256) combine_kernel(float* __restrict__ out) {
    const int nq = Ntok * (Dd / 4);
    for (int idx = blockIdx.x * blockDim.x + threadIdx.x; idx < nq;
         idx += gridDim.x * blockDim.x) {
        int t = idx / (Dd / 4);
        int dq = idx - t * (Dd / 4);
        int p0 = g_pos[t * 2 + 0], p1 = g_pos[t * 2 + 1];
        float w0 = g_tok_w[t * 2 + 0], w1 = g_tok_w[t * 2 + 1];
        float4 a = *(const float4*)(g_y + (size_t)p0 * Dd + dq * 4);
        float4 b = *(const float4*)(g_y + (size_t)p1 * Dd + dq * 4);
        float4 o;
        o.x = w0 * a.x + w1 * b.x;
        o.y = w0 * a.y + w1 * b.y;
        o.z = w0 * a.z + w1 * b.z;
        o.w = w0 * a.w + w1 * b.w;
        *(float4*)(out + (size_t)t * Dd + dq * 4) = o;
    }
}

// ======================= aux loss =======================
__global__ void __launch_bounds__(32) aux_kernel(float* __restrict__ out, int out_size) {
    if (threadIdx.x != 0 || blockIdx.x != 0) return;
    float s = 0.0f;
    for (int e = 0; e < Ee; e++) {
        float load = g_load[e] / (float)Ntok;
        float frac = (float)g_counts[e] / (float)(Ntok * TOPK);
        s += frac * load;
    }
    float aux = 0.01f * (float)Ee * s;
    for (int i = Ntok * Dd; i < out_size; i++) out[i] = aux;
}

// ======================= launch =======================
extern "C" void kernel_launch(void* const* d_in, const int* in_sizes, int n_in,
                              void* d_out, int out_size) {
    const float* x      = (const float*)d_in[0];
    const float* gate_w = (const float*)d_in[1];
    const float* w_gate = (const float*)d_in[2];
    const float* w_up   = (const float*)d_in[3];
    const float* w_down = (const float*)d_in[4];
    float* out = (float*)d_out;

    cudaFuncSetAttribute(gemm1_mma_kernel, cudaFuncAttributeMaxDynamicSharedMemorySize, SMEM_TOT);
    cudaFuncSetAttribute(gemm2_mma_kernel, cudaFuncAttributeMaxDynamicSharedMemorySize, SMEM_TOT);

    zero_meta_kernel<<<1, 32>>>();
    split_x_kernel<<<(Ntok * Dd / 4 + 255) / 256, 256>>>(x);

    __nv_bfloat16 *wg_hi_p, *wg_lo_p, *wu_hi_p, *wu_lo_p, *wd_hi_p, *wd_lo_p;
    cudaGetSymbolAddress((void**)&wg_hi_p, g_wg_hi);
    cudaGetSymbolAddress((void**)&wg_lo_p, g_wg_lo);
    cudaGetSymbolAddress((void**)&wu_hi_p, g_wu_hi);
    cudaGetSymbolAddress((void**)&wu_lo_p, g_wu_lo);
    cudaGetSymbolAddress((void**)&wd_hi_p, g_wd_hi);
    cudaGetSymbolAddress((void**)&wd_lo_p, g_wd_lo);

    dim3 tb(32, 8);
    tsplit_kernel<<<dim3(Ff / 32, Dd / 32, Ee), tb>>>(w_gate, wg_hi_p, wg_lo_p, Dd, Ff);
    tsplit_kernel<<<dim3(Ff / 32, Dd / 32, Ee), tb>>>(w_up,   wu_hi_p, wu_lo_p, Dd, Ff);
    tsplit_kernel<<<dim3(Dd / 32, Ff / 32, Ee), tb>>>(w_down, wd_hi_p, wd_lo_p, Ff, Dd);

    gate_kernel<<<Ntok / 4, 128>>>(x, gate_w);
    scan_kernel<<<1, 32>>>();
    build_kernel<<<(Ntok + 255) / 256, 256>>>();

    gemm1_mma_kernel<<<dim3(Ff / 64, 136), 256, SMEM_TOT>>>();
    gemm2_mma_kernel<<<dim3(Dd / 128, 136), 256, SMEM_TOT>>>();

    combine_kernel<<<1184, 256>>>(out);
    aux_kernel<<<1, 32>>>(out, out_size);
}

// round 7
// speedup vs baseline: 2.7668x; 1.1829x over previous
#include <cuda_runtime.h>
#include <cuda_bf16.h>
#include <stdint.h>
#include <math.h>

#define Bt 4
#define Tt 2048
#define Dd 1024
#define Ee 8
#define Ff 2752
#define TOPK 2
#define Ntok (Bt*Tt)        // 8192 tokens
#define NR   (Ntok*TOPK)    // 16384 routed rows

// ======================= device scratch (static, no allocs) =======================
__device__ __nv_bfloat16 g_x_hi[(size_t)Ntok * Dd];
__device__ __nv_bfloat16 g_x_lo[(size_t)Ntok * Dd];
__device__ __nv_bfloat16 g_wg_hi[(size_t)Ee * Ff * Dd];   // [e][n(F)][k(D)]
__device__ __nv_bfloat16 g_wg_lo[(size_t)Ee * Ff * Dd];
__device__ __nv_bfloat16 g_wu_hi[(size_t)Ee * Ff * Dd];
__device__ __nv_bfloat16 g_wu_lo[(size_t)Ee * Ff * Dd];
__device__ __nv_bfloat16 g_wd_hi[(size_t)Ee * Dd * Ff];   // [e][n(D)][k(F)]
__device__ __nv_bfloat16 g_wd_lo[(size_t)Ee * Dd * Ff];
__device__ __nv_bfloat16 g_h_hi[(size_t)NR * Ff];         // [r][f]
__device__ __nv_bfloat16 g_h_lo[(size_t)NR * Ff];
__device__ float g_y[(size_t)NR * Dd];
__device__ int   g_row_token[NR];
__device__ int   g_pos[Ntok * TOPK];
__device__ int   g_tok_eid[Ntok * TOPK];
__device__ float g_tok_w[Ntok * TOPK];
__device__ int   g_counts[Ee];
__device__ int   g_offs[Ee + 1];
__device__ int   g_cursor[Ee];
__device__ int   g_tile_off[Ee + 1];
__device__ float g_load[Ee];

// ======================= helpers =======================
__device__ __forceinline__ uint32_t smem_u32(const void* p) {
    uint32_t a;
    asm("{ .reg .u64 t; cvta.to.shared.u64 t, %1; cvt.u32.u64 %0, t; }" : "=r"(a) : "l"(p));
    return a;
}

#define CPASYNC(dst, src) \
    asm volatile("cp.async.cg.shared.global [%0], [%1], 16;" :: "r"(dst), "l"(src) : "memory")
#define CPCOMMIT() asm volatile("cp.async.commit_group;" ::: "memory")
#define CPWAIT1()  asm volatile("cp.async.wait_group 1;" ::: "memory")
#define CPWAIT0()  asm volatile("cp.async.wait_group 0;" ::: "memory")

#define LDMX4(r0, r1, r2, r3, a) \
    asm volatile("ldmatrix.sync.aligned.m8n8.x4.shared.b16 {%0,%1,%2,%3}, [%4];" \
        : "=r"(r0), "=r"(r1), "=r"(r2), "=r"(r3) : "r"(a))

#define MMA_BF16(c, a, b) \
    asm volatile("mma.sync.aligned.m16n8k16.row.col.f32.bf16.bf16.f32 " \
        "{%0,%1,%2,%3}, {%4,%5,%6,%7}, {%8,%9}, {%0,%1,%2,%3};" \
        : "+f"((c)[0]), "+f"((c)[1]), "+f"((c)[2]), "+f"((c)[3]) \
        : "r"((a)[0]), "r"((a)[1]), "r"((a)[2]), "r"((a)[3]), "r"((b)[0]), "r"((b)[1]))

// padded row stride: 32 halves + 8 pad = 40 halves = 80 bytes (16B-aligned; r*80 mod 128
// is an 8-cycle => conflict-free for both cp.async stores and ldmatrix 8-row phases)
#define RSTR 80
#define A_TILE_B (128 * RSTR)        // 10240
#define B_TILE_B (64 * RSTR)         // 5120
#define G1_STAGE (2 * A_TILE_B + 4 * B_TILE_B)      // 40960
#define G2_STAGE (2 * A_TILE_B + 2 * (128 * RSTR))  // 40960
#define SMEM_TOT (2 * 40960 + 512)

// ======================= pass 0: zero metadata =======================
__global__ void __launch_bounds__(32) zero_meta_kernel() {
    int t = threadIdx.x;
    if (t < Ee) { g_counts[t] = 0; g_load[t] = 0.0f; }
}

// ======================= prep: split x to bf16 hi/lo =======================
__global__ void __launch_bounds__(256) split_x_kernel(const float* __restrict__ x) {
    int i = (blockIdx.x * 256 + threadIdx.x) * 4;
    if (i >= Ntok * Dd) return;
    float4 v = *(const float4*)(x + i);
    float vv[4] = {v.x, v.y, v.z, v.w};
    __nv_bfloat16 hh[4], ll[4];
#pragma unroll
    for (int q = 0; q < 4; q++) {
        hh[q] = __float2bfloat16(vv[q]);
        ll[q] = __float2bfloat16(vv[q] - __bfloat162float(hh[q]));
    }
    *(uint2*)(g_x_hi + i) = *(uint2*)hh;
    *(uint2*)(g_x_lo + i) = *(uint2*)ll;
}

// ======================= prep: transpose + split weights =======================
__global__ void __launch_bounds__(256) tsplit_kernel(const float* __restrict__ src,
                                                     __nv_bfloat16* __restrict__ dhi,
                                                     __nv_bfloat16* __restrict__ dlo,
                                                     int K, int N) {
    __shared__ float t[32][33];
    size_t base = (size_t)blockIdx.z * K * N;
    int n0 = blockIdx.x * 32, k0 = blockIdx.y * 32;
#pragma unroll
    for (int i = 0; i < 4; i++) {
        int k = k0 + threadIdx.y + i * 8;
        t[threadIdx.y + i * 8][threadIdx.x] = src[base + (size_t)k * N + n0 + threadIdx.x];
    }
    __syncthreads();
#pragma unroll
    for (int i = 0; i < 4; i++) {
        int n = n0 + threadIdx.y + i * 8;
        float v = t[threadIdx.x][threadIdx.y + i * 8];
        __nv_bfloat16 hi = __float2bfloat16(v);
        size_t o = base + (size_t)n * K + k0 + threadIdx.x;
        dhi[o] = hi;
        dlo[o] = __float2bfloat16(v - __bfloat162float(hi));
    }
}

// ======================= gating (one warp per token, exact fp32) =======================
__global__ void __launch_bounds__(128) gate_kernel(const float* __restrict__ x,
                                                   const float* __restrict__ gw) {
    int warp = (blockIdx.x * blockDim.x + threadIdx.x) >> 5;
    int lane = threadIdx.x & 31;
    if (warp >= Ntok) return;
    const float* xr = x + (size_t)warp * Dd;
    float xv[32];
#pragma unroll
    for (int j = 0; j < 32; j++) xv[j] = xr[j * 32 + lane];
    float p[Ee];
#pragma unroll
    for (int e = 0; e < Ee; e++) {
        float s = 0.0f;
#pragma unroll
        for (int j = 0; j < 32; j++) s += xv[j] * gw[(j * 32 + lane) * Ee + e];
#pragma unroll
        for (int o = 16; o; o >>= 1) s += __shfl_xor_sync(0xffffffffu, s, o);
        p[e] = s;
    }
    float mx = p[0];
#pragma unroll
    for (int e = 1; e < Ee; e++) mx = fmaxf(mx, p[e]);
    float den = 0.0f;
#pragma unroll
    for (int e = 0; e < Ee; e++) { p[e] = expf(p[e] - mx); den += p[e]; }
    float inv = 1.0f / den;
#pragma unroll
    for (int e = 0; e < Ee; e++) p[e] *= inv;
    int i1 = 0;
#pragma unroll
    for (int e = 1; e < Ee; e++) if (p[e] > p[i1]) i1 = e;
    int i2 = -1; float b2 = -1.0f;
#pragma unroll
    for (int e = 0; e < Ee; e++) {
        if (e == i1) continue;
        if (p[e] > b2) { b2 = p[e]; i2 = e; }
    }
    float s2 = p[i1] + p[i2] + 1e-8f;
    if (lane == 0) {
        g_tok_eid[warp * 2 + 0] = i1;
        g_tok_eid[warp * 2 + 1] = i2;
        g_tok_w[warp * 2 + 0] = p[i1] / s2;
        g_tok_w[warp * 2 + 1] = p[i2] / s2;
        atomicAdd(&g_counts[i1], 1);
        atomicAdd(&g_counts[i2], 1);
#pragma unroll
        for (int e = 0; e < Ee; e++) atomicAdd(&g_load[e], p[e]);
    }
}

// ======================= scan =======================
__global__ void __launch_bounds__(32) scan_kernel() {
    if (threadIdx.x != 0) return;
    int s = 0, ts = 0;
    for (int e = 0; e < Ee; e++) {
        g_offs[e] = s; g_cursor[e] = s; g_tile_off[e] = ts;
        ts += (g_counts[e] + 127) / 128;
        s += g_counts[e];
    }
    g_offs[Ee] = s; g_tile_off[Ee] = ts;
}

// ======================= routing build =======================
__global__ void __launch_bounds__(256) build_kernel() {
    int t = blockIdx.x * blockDim.x + threadIdx.x;
    if (t >= Ntok) return;
#pragma unroll
    for (int k = 0; k < TOPK; k++) {
        int e = g_tok_eid[t * 2 + k];
        int r = atomicAdd(&g_cursor[e], 1);
        g_row_token[r] = t;
        g_pos[t * 2 + k] = r;
    }
}

// ======================= gemm1: h = silu(Xg Wg) * (Xg Wu), mma.sync 3xbf16 =======================
extern "C" __global__ void __launch_bounds__(256, 2)
gemm1_mma_kernel() {
    extern __shared__ __align__(16) char smem[];
    int tid = threadIdx.x, wid = tid >> 5, lane = tid & 31;
    int grp = lane >> 2, tig = lane & 3;

    int j = blockIdx.y;
    if (j >= g_tile_off[Ee]) return;
    int e = 0;
#pragma unroll
    for (int q = 0; q < Ee - 1; q++) if (j >= g_tile_off[q + 1]) e = q + 1;
    int mt0 = j - g_tile_off[e];
    int rowStart = g_offs[e] + mt0 * 128;
    int end = g_offs[e + 1];
    int n0 = blockIdx.x * 64;

    uint32_t sb = smem_u32(smem);
    int* tokS = (int*)(smem + 2 * G1_STAGE);
    if (tid < 128) {
        int rr = rowStart + tid; if (rr > end - 1) rr = end - 1;
        tokS[tid] = g_row_token[rr];
    }
    __syncthreads();

    const __nv_bfloat16* wb[4];
    wb[0] = g_wg_hi + ((size_t)e * Ff + n0) * Dd;
    wb[1] = g_wg_lo + ((size_t)e * Ff + n0) * Dd;
    wb[2] = g_wu_hi + ((size_t)e * Ff + n0) * Dd;
    wb[3] = g_wu_lo + ((size_t)e * Ff + n0) * Dd;

    float cg[2][4][4] = {}, cu[2][4][4] = {};
    const int NIT = Dd / 32;   // 32

    // lane-invariant ldmatrix offsets
    int mwbase = (wid & 3) * 32;
    int nwbase = (wid >> 2) * 32;
    uint32_t aoff = (uint32_t)((mwbase + (lane & 15)) * RSTR + (lane >> 4) * 16);
    uint32_t boff = (uint32_t)(2 * A_TILE_B +
                               (nwbase + ((lane >> 4) * 8) + (lane & 7)) * RSTR +
                               (((lane >> 3) & 1) * 16));

    auto issue = [&](int it) {
        uint32_t stu = sb + (it & 1) * G1_STAGE;
        int k0 = it * 32;
#pragma unroll
        for (int q = 0; q < 8; q++) {
            int c = tid + q * 256;
            if (c < 1024) {                     // A hi/lo: 2*128 rows * 4 chunks
                int arr = c >> 9, idx = c & 511, row = idx >> 2, cc = idx & 3;
                const __nv_bfloat16* src =
                    (arr ? g_x_lo : g_x_hi) + (size_t)tokS[row] * Dd + k0 + cc * 8;
                uint32_t dst = stu + arr * A_TILE_B + row * RSTR + cc * 16;
                CPASYNC(dst, src);
            } else {                            // B: 4 mats * 64 rows * 4 chunks
                int b = c - 1024, mat = b >> 8, idx = b & 255, row = idx >> 2, cc = idx & 3;
                const __nv_bfloat16* src = wb[mat] + (size_t)row * Dd + k0 + cc * 8;
                uint32_t dst = stu + 2 * A_TILE_B + mat * B_TILE_B + row * RSTR + cc * 16;
                CPASYNC(dst, src);
            }
        }
        CPCOMMIT();
    };

    issue(0);
    for (int it = 0; it < NIT; it++) {
        if (it + 1 < NIT) { issue(it + 1); CPWAIT1(); } else { CPWAIT0(); }
        __syncthreads();
        uint32_t stu = sb + (it & 1) * G1_STAGE;
#pragma unroll
        for (int ks = 0; ks < 2; ks++) {
            uint32_t kb = ks * 32;
            uint32_t ah[2][4], al[2][4];
#pragma unroll
            for (int mt = 0; mt < 2; mt++) {
                uint32_t ab = stu + aoff + mt * (16 * RSTR) + kb;
                LDMX4(ah[mt][0], ah[mt][1], ah[mt][2], ah[mt][3], ab);
                LDMX4(al[mt][0], al[mt][1], al[mt][2], al[mt][3], ab + A_TILE_B);
            }
#pragma unroll
            for (int ntp = 0; ntp < 2; ntp++) {
                uint32_t bb = stu + boff + ntp * (16 * RSTR) + kb;
                uint32_t gh[4], gl[4], uh[4], ul[4];
                LDMX4(gh[0], gh[1], gh[2], gh[3], bb);
                LDMX4(gl[0], gl[1], gl[2], gl[3], bb + B_TILE_B);
                LDMX4(uh[0], uh[1], uh[2], uh[3], bb + 2 * B_TILE_B);
                LDMX4(ul[0], ul[1], ul[2], ul[3], bb + 3 * B_TILE_B);
#pragma unroll
                for (int s2 = 0; s2 < 2; s2++) {
                    int nt = ntp * 2 + s2;
                    uint32_t bgh[2] = {gh[2 * s2], gh[2 * s2 + 1]};
                    uint32_t bgl[2] = {gl[2 * s2], gl[2 * s2 + 1]};
                    uint32_t buh[2] = {uh[2 * s2], uh[2 * s2 + 1]};
                    uint32_t bul[2] = {ul[2 * s2], ul[2 * s2 + 1]};
#pragma unroll
                    for (int mt = 0; mt < 2; mt++) {
                        MMA_BF16(cg[mt][nt], ah[mt], bgh);
                        MMA_BF16(cg[mt][nt], al[mt], bgh);
                        MMA_BF16(cg[mt][nt], ah[mt], bgl);
                        MMA_BF16(cu[mt][nt], ah[mt], buh);
                        MMA_BF16(cu[mt][nt], al[mt], buh);
                        MMA_BF16(cu[mt][nt], ah[mt], bul);
                    }
                }
            }
        }
        __syncthreads();
    }

    // epilogue: SwiGLU, split to bf16 hi/lo, store
#pragma unroll
    for (int mt = 0; mt < 2; mt++) {
#pragma unroll
        for (int half = 0; half < 2; half++) {
            int row = rowStart + mwbase + mt * 16 + grp + half * 8;
            if (row >= end) continue;
#pragma unroll
            for (int nt = 0; nt < 4; nt++) {
                int col = n0 + nwbase + nt * 8 + tig * 2;
                float g0 = cg[mt][nt][half * 2], g1 = cg[mt][nt][half * 2 + 1];
                float u0 = cu[mt][nt][half * 2], u1 = cu[mt][nt][half * 2 + 1];
                float z0 = g0 / (1.0f + expf(-g0)) * u0;
                float z1 = g1 / (1.0f + expf(-g1)) * u1;
                __nv_bfloat16 h0 = __float2bfloat16(z0);
                __nv_bfloat16 h1 = __float2bfloat16(z1);
                __nv_bfloat16 l0 = __float2bfloat16(z0 - __bfloat162float(h0));
                __nv_bfloat16 l1 = __float2bfloat16(z1 - __bfloat162float(h1));
                __nv_bfloat162 hv; hv.x = h0; hv.y = h1;
                __nv_bfloat162 lv; lv.x = l0; lv.y = l1;
                *(__nv_bfloat162*)(g_h_hi + (size_t)row * Ff + col) = hv;
                *(__nv_bfloat162*)(g_h_lo + (size_t)row * Ff + col) = lv;
            }
        }
    }
}

// ======================= gemm2: y = h @ Wd, mma.sync 3xbf16 =======================
extern "C" __global__ void __launch_bounds__(256, 2)
gemm2_mma_kernel() {
    extern __shared__ __align__(16) char smem[];
    int tid = threadIdx.x, wid = tid >> 5, lane = tid & 31;
    int grp = lane >> 2, tig = lane & 3;

    int j = blockIdx.y;
    if (j >= g_tile_off[Ee]) return;
    int e = 0;
#pragma unroll
    for (int q = 0; q < Ee - 1; q++) if (j >= g_tile_off[q + 1]) e = q + 1;
    int mt0 = j - g_tile_off[e];
    int rowStart = g_offs[e] + mt0 * 128;
    int end = g_offs[e + 1];
    int n0 = blockIdx.x * 128;

    uint32_t sb = smem_u32(smem);
    const __nv_bfloat16* wdh = g_wd_hi + ((size_t)e * Dd + n0) * Ff;
    const __nv_bfloat16* wdl = g_wd_lo + ((size_t)e * Dd + n0) * Ff;

    float cc_[2][8][4] = {};
    const int NIT = Ff / 32;    // 86
    const int BT = 128 * RSTR;  // 10240

    int mwbase = (wid & 3) * 32;
    int nwbase = (wid >> 2) * 64;
    uint32_t aoff = (uint32_t)((mwbase + (lane & 15)) * RSTR + (lane >> 4) * 16);
    uint32_t boff = (uint32_t)(2 * A_TILE_B +
                               (nwbase + ((lane >> 4) * 8) + (lane & 7)) * RSTR +
                               (((lane >> 3) & 1) * 16));

    auto issue = [&](int it) {
        uint32_t stu = sb + (it & 1) * G2_STAGE;
        int k0 = it * 32;
#pragma unroll
        for (int q = 0; q < 8; q++) {
            int c = tid + q * 256;
            if (c < 1024) {                     // A (h) hi/lo
                int arr = c >> 9, idx = c & 511, row = idx >> 2, ck = idx & 3;
                int rr = rowStart + row; if (rr > end - 1) rr = end - 1;
                const __nv_bfloat16* src =
                    (arr ? g_h_lo : g_h_hi) + (size_t)rr * Ff + k0 + ck * 8;
                uint32_t dst = stu + arr * A_TILE_B + row * RSTR + ck * 16;
                CPASYNC(dst, src);
            } else {                            // B (wd) hi/lo
                int b = c - 1024, arr = b >> 9, idx = b & 511, row = idx >> 2, ck = idx & 3;
                const __nv_bfloat16* src = (arr ? wdl : wdh) + (size_t)row * Ff + k0 + ck * 8;
                uint32_t dst = stu + 2 * A_TILE_B + arr * BT + row * RSTR + ck * 16;
                CPASYNC(dst, src);
            }
        }
        CPCOMMIT();
    };

    issue(0);
    for (int it = 0; it < NIT; it++) {
        if (it + 1 < NIT) { issue(it + 1); CPWAIT1(); } else { CPWAIT0(); }
        __syncthreads();
        uint32_t stu = sb + (it & 1) * G2_STAGE;
#pragma unroll
        for (int ks = 0; ks < 2; ks++) {
            uint32_t kb = ks * 32;
            uint32_t ah[2][4], al[2][4];
#pragma unroll
            for (int mt = 0; mt < 2; mt++) {
                uint32_t ab = stu + aoff + mt * (16 * RSTR) + kb;
                LDMX4(ah[mt][0], ah[mt][1], ah[mt][2], ah[mt][3], ab);
                LDMX4(al[mt][0], al[mt][1], al[mt][2], al[mt][3], ab + A_TILE_B);
            }
#pragma unroll
            for (int ntp = 0; ntp < 4; ntp++) {
                uint32_t bb = stu + boff + ntp * (16 * RSTR) + kb;
                uint32_t bh4[4], bl4[4];
                LDMX4(bh4[0], bh4[1], bh4[2], bh4[3], bb);
                LDMX4(bl4[0], bl4[1], bl4[2], bl4[3], bb + BT);
#pragma unroll
                for (int s2 = 0; s2 < 2; s2++) {
                    int nt = ntp * 2 + s2;
                    uint32_t bh[2] = {bh4[2 * s2], bh4[2 * s2 + 1]};
                    uint32_t bl[2] = {bl4[2 * s2], bl4[2 * s2 + 1]};
#pragma unroll
                    for (int mt = 0; mt < 2; mt++) {
                        MMA_BF16(cc_[mt][nt], ah[mt], bh);
                        MMA_BF16(cc_[mt][nt], al[mt], bh);
                        MMA_BF16(cc_[mt][nt], ah[mt], bl);
                    }
                }
            }
        }
        __syncthreads();
    }

#pragma unroll
    for (int mt = 0; mt < 2; mt++) {
#pragma unroll
        for (int half = 0; half < 2; half++) {
            int row = rowStart + mwbase + mt * 16 + grp + half * 8;
            if (row >= end) continue;
#pragma unroll
            for (int nt = 0; nt < 8; nt++) {
                int col = n0 + nwbase + nt * 8 + tig * 2;
                float2 v = make_float2(cc_[mt][nt][half * 2], cc_[mt][nt][half * 2 + 1]);
                *(float2*)(g_y + (size_t)row * Dd + col) = v;
            }
        }
    }
}

// ======================= combine =======================
__global__ void __launch_bounds__(256) combine_kernel(float* __restrict__ out) {
    const int nq = Ntok * (Dd / 4);
    for (int idx = blockIdx.x * blockDim.x + threadIdx.x; idx < nq;
         idx += gridDim.x * blockDim.x) {
        int t = idx / (Dd / 4);
        int dq = idx - t * (Dd / 4);
        int p0 = g_pos[t * 2 + 0], p1 = g_pos[t * 2 + 1];
        float w0 = g_tok_w[t * 2 + 0], w1 = g_tok_w[t * 2 + 1];
        float4 a = *(const float4*)(g_y + (size_t)p0 * Dd + dq * 4);
        float4 b = *(const float4*)(g_y + (size_t)p1 * Dd + dq * 4);
        float4 o;
        o.x = w0 * a.x + w1 * b.x;
        o.y = w0 * a.y + w1 * b.y;
        o.z = w0 * a.z + w1 * b.z;
        o.w = w0 * a.w + w1 * b.w;
        *(float4*)(out + (size_t)t * Dd + dq * 4) = o;
    }
}

// ======================= aux loss =======================
__global__ void __launch_bounds__(32) aux_kernel(float* __restrict__ out, int out_size) {
    if (threadIdx.x != 0 || blockIdx.x != 0) return;
    float s = 0.0f;
    for (int e = 0; e < Ee; e++) {
        float load = g_load[e] / (float)Ntok;
        float frac = (float)g_counts[e] / (float)(Ntok * TOPK);
        s += frac * load;
    }
    float aux = 0.01f * (float)Ee * s;
    for (int i = Ntok * Dd; i < out_size; i++) out[i] = aux;
}

// ======================= launch =======================
extern "C" void kernel_launch(void* const* d_in, const int* in_sizes, int n_in,
                              void* d_out, int out_size) {
    const float* x      = (const float*)d_in[0];
    const float* gate_w = (const float*)d_in[1];
    const float* w_gate = (const float*)d_in[2];
    const float* w_up   = (const float*)d_in[3];
    const float* w_down = (const float*)d_in[4];
    float* out = (float*)d_out;

    cudaFuncSetAttribute(gemm1_mma_kernel, cudaFuncAttributeMaxDynamicSharedMemorySize, SMEM_TOT);
    cudaFuncSetAttribute(gemm2_mma_kernel, cudaFuncAttributeMaxDynamicSharedMemorySize, SMEM_TOT);

    zero_meta_kernel<<<1, 32>>>();
    split_x_kernel<<<(Ntok * Dd / 4 + 255) / 256, 256>>>(x);

    __nv_bfloat16 *wg_hi_p, *wg_lo_p, *wu_hi_p, *wu_lo_p, *wd_hi_p, *wd_lo_p;
    cudaGetSymbolAddress((void**)&wg_hi_p, g_wg_hi);
    cudaGetSymbolAddress((void**)&wg_lo_p, g_wg_lo);
    cudaGetSymbolAddress((void**)&wu_hi_p, g_wu_hi);
    cudaGetSymbolAddress((void**)&wu_lo_p, g_wu_lo);
    cudaGetSymbolAddress((void**)&wd_hi_p, g_wd_hi);
    cudaGetSymbolAddress((void**)&wd_lo_p, g_wd_lo);

    dim3 tb(32, 8);
    tsplit_kernel<<<dim3(Ff / 32, Dd / 32, Ee), tb>>>(w_gate, wg_hi_p, wg_lo_p, Dd, Ff);
    tsplit_kernel<<<dim3(Ff / 32, Dd / 32, Ee), tb>>>(w_up,   wu_hi_p, wu_lo_p, Dd, Ff);
    tsplit_kernel<<<dim3(Dd / 32, Ff / 32, Ee), tb>>>(w_down, wd_hi_p, wd_lo_p, Ff, Dd);

    gate_kernel<<<Ntok / 4, 128>>>(x, gate_w);
    scan_kernel<<<1, 32>>>();
    build_kernel<<<(Ntok + 255) / 256, 256>>>();

    gemm1_mma_kernel<<<dim3(Ff / 64, 136), 256, SMEM_TOT>>>();
    gemm2_mma_kernel<<<dim3(Dd / 128, 136), 256, SMEM_TOT>>>();

    combine_kernel<<<1184, 256>>>(out);
    aux_kernel<<<1, 32>>>(out, out_size);
}